// round 1
// baseline (speedup 1.0000x reference)
#include <cuda_runtime.h>

// ProdAt: x [16384, 8192] fp32 -> out [16384, 128] fp32
// out[b][s] = prod_{i=0..63} x[b][s*64 + i]
//
// One half-warp per segment: 16 lanes x float4 = 64 floats (256B contiguous).
// Full warp covers 2 adjacent segments = 512B contiguous per warp-load.

static constexpr long long N_SEGMENTS_TOTAL = 16384LL * 128LL;  // 2,097,152

__global__ void __launch_bounds__(256) prodat_kernel(
    const float* __restrict__ x, float* __restrict__ out)
{
    // global warp index
    const long long warp_id =
        (long long)blockIdx.x * (blockDim.x >> 5) + (threadIdx.x >> 5);
    const int lane = threadIdx.x & 31;

    // 2 segments per warp; lanes 0-15 -> seg 2w, lanes 16-31 -> seg 2w+1
    const long long seg = warp_id * 2 + (lane >> 4);
    const int sub = lane & 15;  // which float4 within the segment

    // segment base in float4 units: seg * 64 floats = seg * 16 float4
    const float4 v = __ldg(reinterpret_cast<const float4*>(x) + seg * 16 + sub);

    float p = (v.x * v.y) * (v.z * v.w);

    // multiply-reduce across the 16 lanes of the half-warp
    #pragma unroll
    for (int off = 8; off > 0; off >>= 1)
        p *= __shfl_xor_sync(0xffffffffu, p, off);

    if (sub == 0)
        out[seg] = p;
}

extern "C" void kernel_launch(void* const* d_in, const int* in_sizes, int n_in,
                              void* d_out, int out_size)
{
    const float* x = (const float*)d_in[0];
    float* out = (float*)d_out;

    // 256 threads = 8 warps = 16 segments per block
    const int threads = 256;
    const long long blocks = N_SEGMENTS_TOTAL / 16;  // 131072, exact

    prodat_kernel<<<(unsigned)blocks, threads>>>(x, out);
}

// round 2
// speedup vs baseline: 1.2678x; 1.2678x over previous
#include <cuda_runtime.h>

// ProdAt: x [16384, 8192] fp32 -> out [16384, 128] fp32
// out[seg] = prod of 64 contiguous floats.
//
// Layout: 8 lanes per segment. Each lane loads f4[sub] and f4[sub+8]
// (both LDG.128 cover one full 128B line per 8-lane group -> perfect
// coalescing). Each thread handles 2 segments -> 4 independent LDG.128
// in flight (MLP=4). Reduction: 3-step shfl_xor within the 8-lane group.

static constexpr long long N_SEGMENTS_TOTAL = 16384LL * 128LL;  // 2,097,152

__device__ __forceinline__ float prod4(float4 v) {
    return (v.x * v.y) * (v.z * v.w);
}

__global__ void __launch_bounds__(256) prodat_kernel(
    const float* __restrict__ x, float* __restrict__ out)
{
    const long long warp_id =
        (long long)blockIdx.x * (blockDim.x >> 5) + (threadIdx.x >> 5);
    const int lane = threadIdx.x & 31;

    const int g   = lane >> 3;   // 0..3 : segment group within warp
    const int sub = lane & 7;    // 0..7 : float4 slot within segment half

    // warp covers 8 consecutive segments: [warp_id*8, warp_id*8+8)
    const long long seg0 = warp_id * 8 + g;       // segments g and g+4
    const long long seg1 = seg0 + 4;

    const float4* x4 = reinterpret_cast<const float4*>(x);

    // issue all 4 loads before any math (MLP = 4)
    const float4 a0 = __ldcs(x4 + seg0 * 16 + sub);
    const float4 b0 = __ldcs(x4 + seg0 * 16 + 8 + sub);
    const float4 a1 = __ldcs(x4 + seg1 * 16 + sub);
    const float4 b1 = __ldcs(x4 + seg1 * 16 + 8 + sub);

    float p0 = prod4(a0) * prod4(b0);
    float p1 = prod4(a1) * prod4(b1);

    // two independent 3-step reductions over the 8-lane group (pipelined)
    #pragma unroll
    for (int off = 4; off > 0; off >>= 1) {
        p0 *= __shfl_xor_sync(0xffffffffu, p0, off);
        p1 *= __shfl_xor_sync(0xffffffffu, p1, off);
    }

    if (sub == 0) {
        out[seg0] = p0;
        out[seg1] = p1;
    }
}

extern "C" void kernel_launch(void* const* d_in, const int* in_sizes, int n_in,
                              void* d_out, int out_size)
{
    const float* x = (const float*)d_in[0];
    float* out = (float*)d_out;

    // 256 threads = 8 warps = 64 segments per block
    const int threads = 256;
    const long long blocks = N_SEGMENTS_TOTAL / 64;  // 32768, exact

    prodat_kernel<<<(unsigned)blocks, threads>>>(x, out);
}

// round 3
// speedup vs baseline: 1.2723x; 1.0036x over previous
#include <cuda_runtime.h>

// ProdAt: x [16384, 8192] fp32 -> out [16384, 128] fp32
// out[seg] = prod of 64 contiguous floats.
//
// 8 lanes per segment (each LDG.128 by an 8-lane group covers one full
// 128B line -> perfect coalescing). Each thread handles 4 segments ->
// 8 independent LDG.128 front-batched (MLP=8). 3-step shfl_xor reduce.

static constexpr long long N_SEGMENTS_TOTAL = 16384LL * 128LL;  // 2,097,152

__device__ __forceinline__ float prod4(float4 v) {
    return (v.x * v.y) * (v.z * v.w);
}

__global__ void __launch_bounds__(256) prodat_kernel(
    const float* __restrict__ x, float* __restrict__ out)
{
    const long long warp_id =
        (long long)blockIdx.x * (blockDim.x >> 5) + (threadIdx.x >> 5);
    const int lane = threadIdx.x & 31;

    const int g   = lane >> 3;   // 0..3 : segment group within warp
    const int sub = lane & 7;    // 0..7 : float4 slot within segment half

    // warp covers 16 consecutive segments: [warp_id*16, warp_id*16+16)
    // this thread: segments base+g, base+g+4, base+g+8, base+g+12
    const long long base = warp_id * 16 + g;

    const float4* x4 = reinterpret_cast<const float4*>(x);

    // front-batch all 8 loads (MLP = 8)
    const float4 a0 = __ldcs(x4 + (base +  0) * 16 + sub);
    const float4 b0 = __ldcs(x4 + (base +  0) * 16 + 8 + sub);
    const float4 a1 = __ldcs(x4 + (base +  4) * 16 + sub);
    const float4 b1 = __ldcs(x4 + (base +  4) * 16 + 8 + sub);
    const float4 a2 = __ldcs(x4 + (base +  8) * 16 + sub);
    const float4 b2 = __ldcs(x4 + (base +  8) * 16 + 8 + sub);
    const float4 a3 = __ldcs(x4 + (base + 12) * 16 + sub);
    const float4 b3 = __ldcs(x4 + (base + 12) * 16 + 8 + sub);

    float p0 = prod4(a0) * prod4(b0);
    float p1 = prod4(a1) * prod4(b1);
    float p2 = prod4(a2) * prod4(b2);
    float p3 = prod4(a3) * prod4(b3);

    // four independent 3-step reductions over the 8-lane group (pipelined)
    #pragma unroll
    for (int off = 4; off > 0; off >>= 1) {
        p0 *= __shfl_xor_sync(0xffffffffu, p0, off);
        p1 *= __shfl_xor_sync(0xffffffffu, p1, off);
        p2 *= __shfl_xor_sync(0xffffffffu, p2, off);
        p3 *= __shfl_xor_sync(0xffffffffu, p3, off);
    }

    if (sub == 0) {
        out[base +  0] = p0;
        out[base +  4] = p1;
        out[base +  8] = p2;
        out[base + 12] = p3;
    }
}

extern "C" void kernel_launch(void* const* d_in, const int* in_sizes, int n_in,
                              void* d_out, int out_size)
{
    const float* x = (const float*)d_in[0];
    float* out = (float*)d_out;

    // 256 threads = 8 warps = 128 segments per block
    const int threads = 256;
    const long long blocks = N_SEGMENTS_TOTAL / 128;  // 16384, exact

    prodat_kernel<<<(unsigned)blocks, threads>>>(x, out);
}